// round 4
// baseline (speedup 1.0000x reference)
#include <cuda_runtime.h>
#include <math.h>

#define DD 2048
#define SS 8192
#define SD (SS*DD)
#define INNER_LR 0.01f

// ---------------- device scratch (static globals; no allocation) ----------------
__device__ float g_q[SD];
__device__ float g_k[SD];
__device__ float g_v[SD];
__device__ float g_h[SD];
__device__ float g_a[SD];
__device__ float g_dy[SD];   // y, then dy in place
__device__ float g_dh[SD];   // da, then dh in place
__device__ float g_T1[SD];   // transpose scratch
__device__ float g_T2[SD];   // transpose scratch
__device__ float g_W2T[DD*DD];
__device__ float g_gW1[DD*DD];
__device__ float g_gW2[DD*DD];
__device__ float g_W1f[DD*DD];
__device__ float g_W2f[DD*DD];
__device__ float g_b1f[DD];
__device__ float g_b2f[DD];
__device__ float g_gb1[DD];
__device__ float g_gb2[DD];
__device__ float g_part[2048];
__device__ float g_alpha;

// ---------------- GEMM: C[M,N] = A[M,K] @ B[N,K]^T (+ bias[n]) ----------------
// All row-major with leading dim = K (A,B) / N (C). M,N multiples of 128; K multiple of 16.
__global__ void __launch_bounds__(256) gemm_nt(
    const float* __restrict__ A, const float* __restrict__ B,
    float* __restrict__ C, const float* __restrict__ bias,
    int Mh, int Nh, int Kh)
{
    __shared__ float As[16][132];
    __shared__ float Bs[16][132];
    const int tid = threadIdx.x;
    const int tx = tid & 15, ty = tid >> 4;
    const int m0 = blockIdx.y * 128, n0 = blockIdx.x * 128;

    float acc[8][8];
#pragma unroll
    for (int i = 0; i < 8; i++)
#pragma unroll
        for (int j = 0; j < 8; j++) acc[i][j] = 0.f;

    for (int k0 = 0; k0 < Kh; k0 += 16) {
#pragma unroll
        for (int v = 0; v < 2; v++) {
            int idx = tid + v * 256;      // 0..511
            int m   = idx >> 2;           // 0..127
            int kq  = (idx & 3) << 2;     // 0,4,8,12
            float4 av = *(const float4*)(A + (size_t)(m0 + m) * Kh + k0 + kq);
            As[kq + 0][m] = av.x; As[kq + 1][m] = av.y;
            As[kq + 2][m] = av.z; As[kq + 3][m] = av.w;
            float4 bv = *(const float4*)(B + (size_t)(n0 + m) * Kh + k0 + kq);
            Bs[kq + 0][m] = bv.x; Bs[kq + 1][m] = bv.y;
            Bs[kq + 2][m] = bv.z; Bs[kq + 3][m] = bv.w;
        }
        __syncthreads();
#pragma unroll
        for (int kk = 0; kk < 16; kk++) {
            float ar[8], br[8];
#pragma unroll
            for (int i = 0; i < 8; i++) ar[i] = As[kk][ty * 8 + i];
#pragma unroll
            for (int j = 0; j < 8; j++) br[j] = Bs[kk][tx * 8 + j];
#pragma unroll
            for (int i = 0; i < 8; i++)
#pragma unroll
                for (int j = 0; j < 8; j++)
                    acc[i][j] = fmaf(ar[i], br[j], acc[i][j]);
        }
        __syncthreads();
    }

#pragma unroll
    for (int i = 0; i < 8; i++) {
        int row = m0 + ty * 8 + i;
#pragma unroll
        for (int j = 0; j < 8; j++) {
            int col = n0 + tx * 8 + j;
            float r = acc[i][j];
            if (bias) r += bias[col];
            C[(size_t)row * Nh + col] = r;
        }
    }
}

// ---------------- transpose: out[C,R] = in[R,C]^T (R,C multiples of 32) ----------------
__global__ void __launch_bounds__(256) transpose_k(
    const float* __restrict__ in, float* __restrict__ out, int R, int Ccols)
{
    __shared__ float tile[32][33];
    int cb = blockIdx.x * 32, rb = blockIdx.y * 32;
    int tx = threadIdx.x & 31, ty = threadIdx.x >> 5;  // 32x8
#pragma unroll
    for (int i = 0; i < 32; i += 8)
        tile[ty + i][tx] = in[(size_t)(rb + ty + i) * Ccols + cb + tx];
    __syncthreads();
#pragma unroll
    for (int i = 0; i < 32; i += 8)
        out[(size_t)(cb + ty + i) * R + rb + tx] = tile[tx][ty + i];
}

// ---------------- row l2-normalize in place: X[r,:] /= max(||X[r,:]||, 1e-12) ----------------
__global__ void __launch_bounds__(256) rownorm_k(float* __restrict__ X)
{
    __shared__ float red[256];
    int r = blockIdx.x;
    int t = threadIdx.x;
    float ss = 0.f;
    for (int c = t; c < DD; c += 256) {
        float v = X[(size_t)r * DD + c];
        ss += v * v;
    }
    red[t] = ss;
    __syncthreads();
    for (int s = 128; s > 0; s >>= 1) {
        if (t < s) red[t] += red[t + s];
        __syncthreads();
    }
    float sc = 1.0f / fmaxf(sqrtf(red[0]), 1e-12f);
    for (int c = t; c < DD; c += 256)
        X[(size_t)r * DD + c] *= sc;
}

// ---------------- elementwise ----------------
__global__ void __launch_bounds__(256) silu_k(const float* __restrict__ h, float* __restrict__ a)
{
    size_t i = (size_t)blockIdx.x * 256 + threadIdx.x;
    float x = h[i];
    float sg = 1.0f / (1.0f + expf(-x));
    a[i] = x * sg;
}

__global__ void __launch_bounds__(256) make_dy_k(const float* __restrict__ v, float* __restrict__ y)
{
    size_t i = (size_t)blockIdx.x * 256 + threadIdx.x;
    y[i] = (y[i] - v[i]) * (2.0f / (float)SD);
}

__global__ void __launch_bounds__(256) make_dh_k(const float* __restrict__ h, float* __restrict__ dh)
{
    size_t i = (size_t)blockIdx.x * 256 + threadIdx.x;
    float x = h[i];
    float sg = 1.0f / (1.0f + expf(-x));
    float ds = sg * (1.0f + x * (1.0f - sg));
    dh[i] *= ds;
}

// ---------------- column sum: out[c] = sum_r M[r,c] ----------------
__global__ void __launch_bounds__(256) colsum_k(const float* __restrict__ M, float* __restrict__ out)
{
    int c = blockIdx.x * 256 + threadIdx.x;
    float s0 = 0.f, s1 = 0.f, s2 = 0.f, s3 = 0.f;
    for (int r = 0; r < SS; r += 4) {
        s0 += M[(size_t)(r + 0) * DD + c];
        s1 += M[(size_t)(r + 1) * DD + c];
        s2 += M[(size_t)(r + 2) * DD + c];
        s3 += M[(size_t)(r + 3) * DD + c];
    }
    out[c] = (s0 + s1) + (s2 + s3);
}

// ---------------- alpha = sigmoid((1/S) * sum_{s,d} x[s,d]*aw[d] + ab) ----------------
__global__ void __launch_bounds__(256) alpha_partial_k(
    const float* __restrict__ x, const float* __restrict__ aw)
{
    __shared__ float red[256];
    int b = blockIdx.x;               // 2048 blocks, each covers 8192 contiguous elems (4 rows)
    size_t base = (size_t)b * 8192;
    int t = threadIdx.x;
    float s = 0.f;
    for (int i = t; i < 8192; i += 256)
        s += x[base + i] * aw[i & (DD - 1)];
    red[t] = s;
    __syncthreads();
    for (int k = 128; k > 0; k >>= 1) {
        if (t < k) red[t] += red[t + k];
        __syncthreads();
    }
    if (t == 0) g_part[b] = red[0];
}

__global__ void __launch_bounds__(256) alpha_final_k(const float* __restrict__ ab)
{
    __shared__ float red[256];
    int t = threadIdx.x;
    float s = 0.f;
    for (int i = t; i < 2048; i += 256) s += g_part[i];
    red[t] = s;
    __syncthreads();
    for (int k = 128; k > 0; k >>= 1) {
        if (t < k) red[t] += red[t + k];
        __syncthreads();
    }
    if (t == 0) {
        float pre = red[0] / (float)SS + ab[0];
        g_alpha = 1.0f / (1.0f + expf(-pre));
    }
}

// ---------------- fast weights ----------------
__global__ void __launch_bounds__(256) fastw_k(
    const float* __restrict__ W, const float* __restrict__ Gm, float* __restrict__ Wf)
{
    size_t i = (size_t)blockIdx.x * 256 + threadIdx.x;
    float am1 = 1.0f - g_alpha;
    Wf[i] = am1 * W[i] - INNER_LR * Gm[i];
}

__global__ void __launch_bounds__(256) fastb_k(
    const float* __restrict__ b1, const float* __restrict__ gb1, float* __restrict__ b1f,
    const float* __restrict__ b2, const float* __restrict__ gb2, float* __restrict__ b2f)
{
    int i = blockIdx.x * 256 + threadIdx.x;
    float am1 = 1.0f - g_alpha;
    b1f[i] = am1 * b1[i] - INNER_LR * gb1[i];
    b2f[i] = am1 * b2[i] - INNER_LR * gb2[i];
}

// ---------------- launch ----------------
extern "C" void kernel_launch(void* const* d_in, const int* in_sizes, int n_in,
                              void* d_out, int out_size)
{
    const float* x   = (const float*)d_in[0];
    const float* W_Q = (const float*)d_in[1];
    const float* W_K = (const float*)d_in[2];
    const float* W_V = (const float*)d_in[3];
    const float* aw  = (const float*)d_in[4];
    const float* ab  = (const float*)d_in[5];
    const float* W1  = (const float*)d_in[6];
    const float* b1  = (const float*)d_in[7];
    const float* W2  = (const float*)d_in[8];
    const float* b2  = (const float*)d_in[9];
    float* out = (float*)d_out;

    float *p_q, *p_k, *p_v, *p_h, *p_a, *p_dy, *p_dh, *p_T1, *p_T2;
    float *p_W2T, *p_gW1, *p_gW2, *p_W1f, *p_W2f, *p_b1f, *p_b2f, *p_gb1, *p_gb2;
    cudaGetSymbolAddress((void**)&p_q,  g_q);
    cudaGetSymbolAddress((void**)&p_k,  g_k);
    cudaGetSymbolAddress((void**)&p_v,  g_v);
    cudaGetSymbolAddress((void**)&p_h,  g_h);
    cudaGetSymbolAddress((void**)&p_a,  g_a);
    cudaGetSymbolAddress((void**)&p_dy, g_dy);
    cudaGetSymbolAddress((void**)&p_dh, g_dh);
    cudaGetSymbolAddress((void**)&p_T1, g_T1);
    cudaGetSymbolAddress((void**)&p_T2, g_T2);
    cudaGetSymbolAddress((void**)&p_W2T, g_W2T);
    cudaGetSymbolAddress((void**)&p_gW1, g_gW1);
    cudaGetSymbolAddress((void**)&p_gW2, g_gW2);
    cudaGetSymbolAddress((void**)&p_W1f, g_W1f);
    cudaGetSymbolAddress((void**)&p_W2f, g_W2f);
    cudaGetSymbolAddress((void**)&p_b1f, g_b1f);
    cudaGetSymbolAddress((void**)&p_b2f, g_b2f);
    cudaGetSymbolAddress((void**)&p_gb1, g_gb1);
    cudaGetSymbolAddress((void**)&p_gb2, g_gb2);

    dim3 blk(256);
    dim3 gSD(DD / 128, SS / 128);   // M=S, N=D GEMMs
    dim3 gDD(DD / 128, DD / 128);   // M=D, N=D GEMMs (K=S)
    int ewBlocks = SD / 256;
    dim3 tSD(DD / 32, SS / 32);     // transpose [S,D] -> [D,S]
    dim3 tDD(DD / 32, DD / 32);

    // alpha = sigmoid(mean(x,1) @ aw^T + ab)
    alpha_partial_k<<<2048, blk>>>(x, aw);
    alpha_final_k<<<1, blk>>>(ab);

    // q,k,v projections
    gemm_nt<<<gSD, blk>>>(x, W_Q, p_q, nullptr, SS, DD, DD);
    gemm_nt<<<gSD, blk>>>(x, W_K, p_k, nullptr, SS, DD, DD);
    gemm_nt<<<gSD, blk>>>(x, W_V, p_v, nullptr, SS, DD, DD);
    rownorm_k<<<SS, blk>>>(p_q);
    rownorm_k<<<SS, blk>>>(p_k);

    // forward mlp on k
    gemm_nt<<<gSD, blk>>>(p_k, W1, p_h, b1, SS, DD, DD);
    silu_k<<<ewBlocks, blk>>>(p_h, p_a);
    gemm_nt<<<gSD, blk>>>(p_a, W2, p_dy, b2, SS, DD, DD);   // y
    make_dy_k<<<ewBlocks, blk>>>(p_v, p_dy);                 // dy = 2(y-v)/(S*D)

    // gW2 = dy^T @ a ; gb2
    transpose_k<<<tSD, blk>>>(p_dy, p_T1, SS, DD);
    transpose_k<<<tSD, blk>>>(p_a,  p_T2, SS, DD);
    gemm_nt<<<gDD, blk>>>(p_T1, p_T2, p_gW2, nullptr, DD, DD, SS);
    colsum_k<<<DD / 256, blk>>>(p_dy, p_gb2);

    // da = dy @ W2 ; dh = da * dsilu(h)
    transpose_k<<<tDD, blk>>>(W2, p_W2T, DD, DD);
    gemm_nt<<<gSD, blk>>>(p_dy, p_W2T, p_dh, nullptr, SS, DD, DD);
    make_dh_k<<<ewBlocks, blk>>>(p_h, p_dh);

    // gW1 = dh^T @ k ; gb1
    transpose_k<<<tSD, blk>>>(p_dh, p_T1, SS, DD);
    transpose_k<<<tSD, blk>>>(p_k,  p_T2, SS, DD);
    gemm_nt<<<gDD, blk>>>(p_T1, p_T2, p_gW1, nullptr, DD, DD, SS);
    colsum_k<<<DD / 256, blk>>>(p_dh, p_gb1);

    // fast weights
    fastw_k<<<(DD * DD) / 256, blk>>>(W1, p_gW1, p_W1f);
    fastw_k<<<(DD * DD) / 256, blk>>>(W2, p_gW2, p_W2f);
    fastb_k<<<DD / 256, blk>>>(b1, p_gb1, p_b1f, b2, p_gb2, p_b2f);

    // retrieve: out = silu(q @ W1f^T + b1f) @ W2f^T + b2f
    gemm_nt<<<gSD, blk>>>(p_q, p_W1f, p_h, p_b1f, SS, DD, DD);
    silu_k<<<ewBlocks, blk>>>(p_h, p_a);
    gemm_nt<<<gSD, blk>>>(p_a, p_W2f, out, p_b2f, SS, DD, DD);
}